// round 7
// baseline (speedup 1.0000x reference)
#include <cuda_runtime.h>

// ---------------------------------------------------------------------------
// GAT collapses (uniform per-item node features; per-dst softmax weights sum
// to 1 via self-loops) => whole model = 7-layer MLP on 64 batch rows.
// 32 blocks x 512 threads; block bx owns rows {2bx, 2bx+1}.
// Thread = (k-half, output): each weight byte LDG'd once per block (wavefront
// optimal), both rows computed per fetch, acts via LDS broadcast, no shuffles;
// 2-way K reduction through one smem float2 exchange. FFMA2 math.
// Weights pre-packed k4-interleaved by pack_kernel (coalesced LDG.128).
// ---------------------------------------------------------------------------

typedef unsigned long long ULL;

__device__ __forceinline__ void ffma2(ULL& d, ULL a, ULL b) {
    asm("fma.rn.f32x2 %0, %1, %2, %0;" : "+l"(d) : "l"(a), "l"(b));
}
__device__ __forceinline__ void fadd2(ULL& d, ULL a) {
    asm("add.rn.f32x2 %0, %1, %0;" : "+l"(d) : "l"(a));
}
__device__ __forceinline__ float2 unpack2f(ULL v) {
    float2 f; asm("mov.b64 {%0, %1}, %2;" : "=f"(f.x), "=f"(f.y) : "l"(v)); return f;
}

// Packed-weight scratch. Per matrix [O x K] (row-major src):
//   dst[off + (k>>2)*O*4 + o*4 + (k&3)] = W[o*K + k]
// -> float4 index (k4*O + o): coalesced LDG.128, 4 consecutive k per lane.
#define OFF_IN   0        // W_in          256 x  64
#define OFF_G0   16384    // gat_W[0]      256 x 256
#define OFF_G1   81920    // gat_W[1]
#define OFF_G2   147456   // gat_W[2]
#define OFF_F    212992   // W_fuse        256 x 320
#define OFF_S1   294912   // [W_p1 ; W_d1] 256 x 256
#define OFF_P2   360448   // W_p2           64 x 128
#define OFF_D2   368640   // W_d2           64 x 128
#define PACK_TOTAL 376832

__device__ __align__(16) float g_packed[PACK_TOTAL];

__global__ void pack_kernel(const float* __restrict__ W_in,
                            const float* __restrict__ gat_W,
                            const float* __restrict__ W_fuse,
                            const float* __restrict__ W_p1,
                            const float* __restrict__ W_d1,
                            const float* __restrict__ W_p2,
                            const float* __restrict__ W_d2) {
    int stride = gridDim.x * blockDim.x;
    for (int e = blockIdx.x * blockDim.x + threadIdx.x; e < PACK_TOTAL; e += stride) {
        const float* src; int le, K, Ocomb, obase, off;
        if (e < 16384)       { src = W_in;           le = e;          K = 64;  Ocomb = 256; obase = 0;   off = OFF_IN; }
        else if (e < 81920)  { src = gat_W;          le = e - 16384;  K = 256; Ocomb = 256; obase = 0;   off = OFF_G0; }
        else if (e < 147456) { src = gat_W + 65536;  le = e - 81920;  K = 256; Ocomb = 256; obase = 0;   off = OFF_G1; }
        else if (e < 212992) { src = gat_W + 131072; le = e - 147456; K = 256; Ocomb = 256; obase = 0;   off = OFF_G2; }
        else if (e < 294912) { src = W_fuse;         le = e - 212992; K = 320; Ocomb = 256; obase = 0;   off = OFF_F;  }
        else if (e < 327680) { src = W_p1;           le = e - 294912; K = 256; Ocomb = 256; obase = 0;   off = OFF_S1; }
        else if (e < 360448) { src = W_d1;           le = e - 327680; K = 256; Ocomb = 256; obase = 128; off = OFF_S1; }
        else if (e < 368640) { src = W_p2;           le = e - 360448; K = 128; Ocomb = 64;  obase = 0;   off = OFF_P2; }
        else                 { src = W_d2;           le = e - 368640; K = 128; Ocomb = 64;  obase = 0;   off = OFF_D2; }
        int o = le / K;
        int k = le - o * K;
        g_packed[off + (k >> 2) * (Ocomb * 4) + (obase + o) * 4 + (k & 3)] = src[le];
    }
}

// Partial dual-row dot over NQ float4-quads starting at quad (sk*NQ).
// Weights packed (float4 idx = k4*O + o), acts broadcast LDS.128.
template<int NQ>
__device__ __forceinline__ float2 partial(const float* __restrict__ base, int o,
                                          int sk, const float* __restrict__ R0,
                                          const float* __restrict__ R1, int O) {
    const longlong2* Wp = (const longlong2*)base + (size_t)(sk * NQ) * O + o;
    const longlong2* a0 = (const longlong2*)R0 + sk * NQ;
    const longlong2* a1 = (const longlong2*)R1 + sk * NQ;
    ULL p0 = 0ull, q0 = 0ull, p1 = 0ull, q1 = 0ull;
    #pragma unroll
    for (int i = 0; i < NQ; i++) {
        longlong2 w  = Wp[(size_t)i * O];
        longlong2 x0 = a0[i];
        longlong2 x1 = a1[i];
        ffma2(p0, (ULL)w.x, (ULL)x0.x);
        ffma2(q0, (ULL)w.y, (ULL)x0.y);
        ffma2(p1, (ULL)w.x, (ULL)x1.x);
        ffma2(q1, (ULL)w.y, (ULL)x1.y);
    }
    fadd2(p0, q0); fadd2(p1, q1);
    float2 f0 = unpack2f(p0), f1 = unpack2f(p1);
    return make_float2(f0.x + f0.y, f1.x + f1.y);
}

__global__ __launch_bounds__(512, 1) void net_kernel(
    const float* __restrict__ x, const int* __restrict__ cidx,
    const float* __restrict__ b_in, const float* __restrict__ gat_b,
    const float* __restrict__ emb, const float* __restrict__ b_fuse,
    const float* __restrict__ b_p1, const float* __restrict__ b_d1,
    const float* __restrict__ b_p2, const float* __restrict__ b_d2,
    const float* __restrict__ W_p3, const float* __restrict__ b_p3,
    const float* __restrict__ W_d3, const float* __restrict__ b_d3,
    float* __restrict__ out) {

    __shared__ __align__(16) float  X0[64], X1[64];
    __shared__ __align__(16) float  A0[336], A1[336], B0[336], B1[336];
    __shared__ __align__(16) float2 P[2][256];           // K-partials (reused 4x128)
    __shared__ __align__(16) float  C0[128], C1[128];

    const int t  = threadIdx.x;
    const int bx = blockIdx.x;
    const int o  = t & 255;     // output feature
    const int kh = t >> 8;      // K half

    // ---- stage inputs: x rows; emb[cidx] -> B[256..319] (fuse tail) ----
    if (t < 32) {
        int r = t >> 4, q = t & 15;
        float4 v = ((const float4*)x)[(2 * bx + r) * 16 + q];
        ((float4*)(r ? X1 : X0))[q] = v;
    } else if (t < 64) {
        int i = t - 32, r = i >> 4, q = i & 15;
        int ci = cidx[2 * bx + r];
        float4 v = ((const float4*)emb)[ci * 16 + q];
        ((float4*)((r ? B1 : B0) + 256))[q] = v;
    }
    __syncthreads();

    // ===== L0: [256 x 64]  X -> A =====
    P[kh][o] = partial<8>(g_packed + OFF_IN, o, kh, X0, X1, 256);
    __syncthreads();
    if (t < 256) {
        float2 u = P[0][t], v = P[1][t]; float b = b_in[t];
        A0[t] = fmaxf(u.x + v.x + b, 0.f);
        A1[t] = fmaxf(u.y + v.y + b, 0.f);
    }
    __syncthreads();

    // ===== L1..L3: collapsed GAT [256 x 256] =====
    P[kh][o] = partial<32>(g_packed + OFF_G0, o, kh, A0, A1, 256);
    __syncthreads();
    if (t < 256) {
        float2 u = P[0][t], v = P[1][t]; float b = gat_b[t];
        B0[t] = fmaxf(u.x + v.x + b, 0.f);
        B1[t] = fmaxf(u.y + v.y + b, 0.f);
    }
    __syncthreads();
    P[kh][o] = partial<32>(g_packed + OFF_G1, o, kh, B0, B1, 256);
    __syncthreads();
    if (t < 256) {
        float2 u = P[0][t], v = P[1][t]; float b = gat_b[256 + t];
        A0[t] = fmaxf(u.x + v.x + b, 0.f);
        A1[t] = fmaxf(u.y + v.y + b, 0.f);
    }
    __syncthreads();
    P[kh][o] = partial<32>(g_packed + OFF_G2, o, kh, A0, A1, 256);
    __syncthreads();
    if (t < 256) {
        float2 u = P[0][t], v = P[1][t]; float b = gat_b[512 + t];
        B0[t] = fmaxf(u.x + v.x + b, 0.f);
        B1[t] = fmaxf(u.y + v.y + b, 0.f);
    }
    __syncthreads();

    // ===== L4: fuse [256 x 320] over [g3 ; emb]  B -> A =====
    P[kh][o] = partial<40>(g_packed + OFF_F, o, kh, B0, B1, 256);
    __syncthreads();
    if (t < 256) {
        float2 u = P[0][t], v = P[1][t]; float b = b_fuse[t];
        A0[t] = fmaxf(u.x + v.x + b, 0.f);
        A1[t] = fmaxf(u.y + v.y + b, 0.f);
    }
    __syncthreads();

    // ===== L5: heads stage1 [p1 ; d1] = [256 x 256]  A -> B =====
    P[kh][o] = partial<32>(g_packed + OFF_S1, o, kh, A0, A1, 256);
    __syncthreads();
    if (t < 256) {
        float2 u = P[0][t], v = P[1][t];
        float b = (t < 128) ? b_p1[t] : b_d1[t - 128];
        B0[t] = fmaxf(u.x + v.x + b, 0.f);
        B1[t] = fmaxf(u.y + v.y + b, 0.f);
    }
    __syncthreads();

    // ===== L6: p2 / d2, each [64 x 128]  B -> C  (4-way K split) =====
    {
        float2 (*P4)[128] = (float2 (*)[128])&P[0][0];
        const int kq = t >> 7;          // K quarter 0..3
        const int o6 = t & 127;         // 0..63 = p2, 64..127 = d2
        const bool is_d = (o6 >= 64);
        const float* base = is_d ? (g_packed + OFF_D2) : (g_packed + OFF_P2);
        const int ol = is_d ? (o6 - 64) : o6;
        const int hb = is_d ? 128 : 0;
        P4[kq][o6] = partial<8>(base, ol, kq, B0 + hb, B1 + hb, 64);
        __syncthreads();
        if (t < 128) {
            float2 s0 = P4[0][t], s1 = P4[1][t], s2 = P4[2][t], s3 = P4[3][t];
            float b2 = (t < 64) ? b_p2[t] : b_d2[t - 64];
            C0[t] = fmaxf(s0.x + s1.x + s2.x + s3.x + b2, 0.f);
            C1[t] = fmaxf(s0.y + s1.y + s2.y + s3.y + b2, 0.f);
        }
    }
    __syncthreads();

    // ===== L7: final 64-dots; warps 0-3 = {r0 price, r0 dir, r1 price, r1 dir}
    const int w = t >> 5, lane = t & 31;
    if (w < 4) {
        const int r = w >> 1, is_d = w & 1;
        const float* W3 = is_d ? W_d3 : W_p3;
        const float* Cv = (r ? C1 : C0) + is_d * 64;
        float v = W3[lane] * Cv[lane] + W3[lane + 32] * Cv[lane + 32];
        #pragma unroll
        for (int m = 16; m; m >>= 1)
            v += __shfl_xor_sync(0xffffffffu, v, m);
        if (lane == 0) {
            int rg = 2 * bx + r;
            if (!is_d) out[rg] = v + b_p3[0];
            else       out[64 + rg] = 1.f / (1.f + __expf(-(v + b_d3[0])));
        }
    }
}

extern "C" void kernel_launch(void* const* d_in, const int* in_sizes, int n_in,
                              void* d_out, int out_size) {
    const float* x      = (const float*)d_in[0];
    const int*   cidx   = (const int*)  d_in[1];
    // d_in[2] edge_index, d_in[3] edge_attr: unused (softmax collapse)
    const float* W_in   = (const float*)d_in[4];
    const float* b_in   = (const float*)d_in[5];
    const float* gat_W  = (const float*)d_in[6];
    // d_in[7..10]: attention params — unused (collapse)
    const float* gat_b  = (const float*)d_in[11];
    const float* emb    = (const float*)d_in[12];
    const float* W_fuse = (const float*)d_in[13];
    const float* b_fuse = (const float*)d_in[14];
    const float* W_p1   = (const float*)d_in[15];
    const float* b_p1   = (const float*)d_in[16];
    const float* W_p2   = (const float*)d_in[17];
    const float* b_p2   = (const float*)d_in[18];
    const float* W_p3   = (const float*)d_in[19];
    const float* b_p3   = (const float*)d_in[20];
    const float* W_d1   = (const float*)d_in[21];
    const float* b_d1   = (const float*)d_in[22];
    const float* W_d2   = (const float*)d_in[23];
    const float* b_d2   = (const float*)d_in[24];
    const float* W_d3   = (const float*)d_in[25];
    const float* b_d3   = (const float*)d_in[26];

    pack_kernel<<<128, 256>>>(W_in, gat_W, W_fuse, W_p1, W_d1, W_p2, W_d2);
    net_kernel<<<32, 512>>>(x, cidx, b_in, gat_b, emb, b_fuse,
                            b_p1, b_d1, b_p2, b_d2,
                            W_p3, b_p3, W_d3, b_d3, (float*)d_out);
}